// round 15
// baseline (speedup 1.0000x reference)
#include <cuda_runtime.h>
#include <math.h>
#include <cstdint>

#define N    3072
#define NT   512
#define NWW  8       // worker warps (warps 1..8)
#define WT   256     // worker threads

#define ANGLE_THR_BITS 0x3FC90FDB   // f32(pi/2)
#define FULLMASK 0xffffffffu
#define INF_F  (__int_as_float(0x7f800000))
#define INFB   0x7f800000u

struct Smem {
    float px[N], py[N], pz[N];     // points (px reused as sort keys later)
    int   slbl[N];                 // per-point class
    int   sdl[N];                  // per-point cluster label
    float ccx[N], ccy[N], ccz[N];  // per-cluster centres
    int   ccount[N], ccls[N];      // per-cluster size / class
    int   order[N];                // scan: member list; post: sort order
    int   items[N];                // scan: compaction buffer; post: class lists
    int   remap[N];                // post: merge remap
    int   selq[N];                 // sel sequence queue (workers -> warp 0)
    unsigned char keep[N];
    unsigned p1A[16], pIdxA[16], p2A[16], p1B[16], pMax[16], psel[16];
    float amdxy[10], amdz[10], ar2[10];
    int   clsCount[10], clsBase[11];
    int   bnc, ccnt;
    float bval; unsigned ordb; int flag0;   // angle threshold data
};

__device__ __forceinline__ float norm3_xla(float x, float y, float z) {
    float s = __fadd_rn(__fadd_rn(__fmul_rn(x, x), __fmul_rn(y, y)), __fmul_rn(z, z));
    return __fsqrt_rn(s);
}
// XLA acos lowering: 2*atan2(sqrt(1-x*x), 1+x); pi at x==-1. Same libdevice atan2f
// as the reference -> bit-identical.
__device__ __forceinline__ float acos_xla(float x) {
    float s = __fsqrt_rn(__fsub_rn(1.0f, __fmul_rn(x, x)));
    float r = 2.0f * atan2f(s, __fadd_rn(1.0f, x));
    if (x == -1.0f) r = __int_as_float(0x40490FDB);
    return r;
}
__device__ __forceinline__ unsigned ford(float f) {
    unsigned u = __float_as_uint(f);
    return (u & 0x80000000u) ? ~u : (u | 0x80000000u);
}
__device__ __forceinline__ float ford_inv(unsigned o) {
    unsigned u = (o & 0x80000000u) ? (o ^ 0x80000000u) : ~o;
    return __uint_as_float(u);
}

// packed f32x2 helpers (two independent IEEE-RN f32 ops per instruction)
__device__ __forceinline__ unsigned long long packf2(float lo, float hi) {
    unsigned long long r;
    asm("mov.b64 %0, {%1, %2};" : "=l"(r) : "f"(lo), "f"(hi));
    return r;
}
__device__ __forceinline__ void unpackf2(unsigned long long p, float& lo, float& hi) {
    asm("mov.b64 {%0, %1}, %2;" : "=f"(lo), "=f"(hi) : "l"(p));
}
__device__ __forceinline__ unsigned long long addf2(unsigned long long a, unsigned long long b) {
    unsigned long long r;
    asm("add.rn.f32x2 %0, %1, %2;" : "=l"(r) : "l"(a), "l"(b));
    return r;
}
__device__ __forceinline__ unsigned long long mulf2(unsigned long long a, unsigned long long b) {
    unsigned long long r;
    asm("mul.rn.f32x2 %0, %1, %2;" : "=l"(r) : "l"(a), "l"(b));
    return r;
}

#define WBAR() asm volatile("bar.sync 1, %0;" :: "r"(WT) : "memory")

// One scan stage: NP pairs (2*NP slots per worker thread).
template<int NP>
__device__ __forceinline__ void worker_stage(
    Smem& S,
    unsigned long long* mxp, unsigned long long* myp, unsigned long long* mzp,
    int* ml, int* jreg,
    int& cls, float& cx, float& cy, float& cz,
    int wtid, int lane, int stepBeg, int stepEnd)
{
    const int wwid = (wtid >> 5) + 1;
    for (int step = stepBeg; step < stepEnd; ++step) {
        unsigned long long ncxp = packf2(-cx, -cx);
        unsigned long long ncyp = packf2(-cy, -cy);
        unsigned long long nczp = packf2(-cz, -cz);

        // ---- pass 1: packed dists; minA(+idx,+min2), minB, max ----
        float m1A = INF_F, m2A = INF_F, m1B = INF_F;
        unsigned maxb = 0u;               // unsigned-0 sentinel (s >= 0)
        unsigned idxA = 0xFFFFFFFFu;
#pragma unroll
        for (int k = 0; k < NP; ++k) {
            unsigned long long dxp = addf2(mxp[k], ncxp);
            unsigned long long dyp = addf2(myp[k], ncyp);
            unsigned long long dzp = addf2(mzp[k], nczp);
            unsigned long long sp  = addf2(addf2(mulf2(dxp,dxp), mulf2(dyp,dyp)),
                                           mulf2(dzp,dzp));
            float s0, s1;
            unpackf2(sp, s0, s1);
#pragma unroll
            for (int h = 0; h < 2; ++h) {
                float s = (h == 0) ? s0 : s1;
                int   l = ml[2*k + h];
                unsigned idx = (unsigned)jreg[2*k + h];
                bool isA  = (l == cls);
                bool live = (l >= 0);
                float sA  = isA ? s : INF_F;
                float sNL = isA ? INF_F : s;
                float sB  = live ? sNL : INF_F;
                maxb = max(maxb, live ? __float_as_uint(s) : 0u);
                bool lt = (sA < m1A);
                idxA = lt ? idx : idxA;
                m2A  = fminf(m2A, fmaxf(m1A, sA));
                m1A  = fminf(m1A, sA);
                m1B  = fminf(m1B, sB);
            }
        }
        // warp-level combine
        unsigned b1A = __reduce_min_sync(FULLMASK, __float_as_uint(m1A));
        unsigned bi  = (__float_as_uint(m1A) == b1A) ? idxA : 0xFFFFFFFFu;
        unsigned bIdxA = __reduce_min_sync(FULLMASK, bi);
        {   // warp second-min with duplicate handling
            unsigned eq  = __ballot_sync(FULLMASK, __float_as_uint(m1A) == b1A);
            unsigned c2  = (__float_as_uint(m1A) == b1A) ? __float_as_uint(m2A)
                                                         : __float_as_uint(m1A);
            unsigned b2A = __reduce_min_sync(FULLMASK, c2);
            if (__popc(eq) >= 2) b2A = b1A;
            unsigned b1B = __reduce_min_sync(FULLMASK, __float_as_uint(m1B));
            unsigned bMx = __reduce_max_sync(FULLMASK, maxb);
            if (lane == 0) {
                S.p1A[wwid] = b1A; S.pIdxA[wwid] = bIdxA; S.p2A[wwid] = b2A;
                S.p1B[wwid] = b1B; S.pMax[wwid] = bMx;
            }
        }
        WBAR();                                            // THE barrier

        // cross-warp combine (all workers, redundant -> identical results)
        unsigned g1A, gIdxA, g2A, g1B, gMx;
        {
            bool ok = (lane >= 1 && lane <= NWW);
            unsigned r1 = ok ? S.p1A[lane]  : INFB;
            unsigned ri = ok ? S.pIdxA[lane]: 0xFFFFFFFFu;
            unsigned r2 = ok ? S.p2A[lane]  : INFB;
            unsigned rb = ok ? S.p1B[lane]  : INFB;
            unsigned rm = ok ? S.pMax[lane] : 0u;
            g1A = __reduce_min_sync(FULLMASK, r1);
            gIdxA = __reduce_min_sync(FULLMASK,
                        (ok && r1 == g1A) ? ri : 0xFFFFFFFFu);
            unsigned eq = __ballot_sync(FULLMASK, ok && r1 == g1A);
            unsigned c2 = ok ? ((r1 == g1A) ? r2 : r1) : INFB;
            g2A = __reduce_min_sync(FULLMASK, c2);
            if (__popc(eq) >= 2) g2A = g1A;
            g1B = __reduce_min_sync(FULLMASK, rb);
            gMx = __reduce_max_sync(FULLMASK, rm);
        }

        const bool hasA = (g1A != INFB), hasB = (g1B != INFB);
        const float dA   = __fsqrt_rn(__uint_as_float(g1A));  // inf if !hasA
        const float dB   = __fsqrt_rn(__uint_as_float(g1B));  // inf if !hasB
        const float dmax = __fsqrt_rn(__uint_as_float(gMx));
        const float dmin = fminf(dA, dB);
        const float Dn   = __fadd_rn(__fsub_rn(dmax, dmin), 1e-8f);

        float costA = INF_F;
        if (hasA) costA = __fdiv_rn(__fsub_rn(dA, dmin), Dn);  // + 0.0f exact

        int sel = -1;
        bool fast = false;
        if (hasA && costA < 1.0f) {
            // conservative s-space admission threshold for class A (over-admit)
            float x = __fmul_ru(costA, Dn);
            x = __fmul_ru(x, 1.000001f);
            x = __fadd_ru(x, 1e-37f);
            float dHi = __fmul_ru(__fadd_ru(dmin, x), 1.0000005f);
            float thrSA = __fmul_ru(__fmul_ru(dHi, dHi), 1.0000005f);
            // fast iff no candidate besides s==g1A can be admitted
            if (thrSA < __uint_as_float(g2A)) { fast = true; sel = (int)gIdxA; }
        }

        if (!fast) {
            // ---- slow path (rare, block-uniform): full generic logic ----
            float costB = INF_F;
            if (hasB) costB = __fadd_rn(__fdiv_rn(__fsub_rn(dB, dmin), Dn), 1.0f);
            float costA2 = hasA ? costA : INF_F;
            float cstar = fminf(costA2, costB);
            float thrSA = -1.0f, thrSB = -1.0f;
            if (hasA && costA2 == cstar) {
                float x = __fmul_ru(cstar, Dn);
                x = __fmul_ru(x, 1.000001f);
                x = __fadd_ru(x, 1e-37f);
                float dHi = __fmul_ru(__fadd_ru(dmin, x), 1.0000005f);
                thrSA = __fmul_ru(__fmul_ru(dHi, dHi), 1.0000005f);
            }
            if (hasB && costB == cstar) {
                float qHi = __fadd_ru(cstar, -1.0f);           // exact (Sterbenz)
                qHi = __fadd_ru(qHi, __fadd_ru(__fmul_ru(cstar, 3e-7f), 1e-37f));
                float x = __fmul_ru(qHi, Dn);
                x = __fmul_ru(x, 1.000001f);
                x = __fadd_ru(x, 1e-37f);
                float dHi = __fmul_ru(__fadd_ru(dmin, x), 1.0000005f);
                thrSB = __fmul_ru(__fmul_ru(dHi, dHi), 1.0000005f);
            }
            unsigned best = 0xFFFFFFFFu;
#pragma unroll
            for (int k = 0; k < NP; ++k) {
                unsigned long long dxp = addf2(mxp[k], ncxp);
                unsigned long long dyp = addf2(myp[k], ncyp);
                unsigned long long dzp = addf2(mzp[k], nczp);
                unsigned long long sp  = addf2(addf2(mulf2(dxp,dxp),
                                                     mulf2(dyp,dyp)),
                                               mulf2(dzp,dzp));
                float s0, s1;
                unpackf2(sp, s0, s1);
#pragma unroll
                for (int h = 0; h < 2; ++h) {
                    float s = (h == 0) ? s0 : s1;
                    int   l = ml[2*k + h];
                    bool live = (l >= 0);
                    bool isA  = (l == cls);
                    float thr = isA ? thrSA : thrSB;
                    if (live && s <= thr) {
                        float d = __fsqrt_rn(s);
                        float q = __fdiv_rn(__fsub_rn(d, dmin), Dn);
                        float c = isA ? q : __fadd_rn(q, 1.0f);
                        if (c == cstar)
                            best = min(best, (unsigned)jreg[2*k + h]);
                    }
                }
            }
            best = __reduce_min_sync(FULLMASK, best);
            if (lane == 0) S.psel[wwid] = best;
            WBAR();
            {
                bool ok = (lane >= 1 && lane <= NWW);
                unsigned v = ok ? S.psel[lane] : 0xFFFFFFFFu;
                sel = (int)__reduce_min_sync(FULLMASK, v);
            }
            if (sel < 0) sel = (int)gIdxA;   // defensive: never publish -1
        }

        // publish sel to the serial engine (one writer)
        if (wtid == 0) ((volatile int*)S.selq)[step] = sel;

        // advance worker state: poison owned slot
#pragma unroll
        for (int k = 0; k < 2*NP; ++k)
            if (jreg[k] == sel) ml[k] = -1;
        cls = S.slbl[sel];
        cx = S.px[sel]; cy = S.py[sel]; cz = S.pz[sel];
    }
}

// Compact live indices into S.items[0..live) and reload NEWS slots per thread.
// Schedule guarantees live == NEWS * WT exactly.
template<int OLDS, int NEWS>
__device__ __forceinline__ void compact_reload(
    Smem& S,
    unsigned long long* mxp, unsigned long long* myp, unsigned long long* mzp,
    int* ml, int* jreg, int wtid, int lane)
{
    if (wtid == 0) S.ccnt = 0;
    WBAR();
#pragma unroll
    for (int k = 0; k < OLDS; ++k) {
        bool live = (ml[k] >= 0);
        unsigned bal = __ballot_sync(FULLMASK, live);
        int cnt = __popc(bal);
        int base = 0;
        if (lane == 0 && cnt) base = atomicAdd(&S.ccnt, cnt);
        base = __shfl_sync(FULLMASK, base, 0);
        if (live) {
            int off = __popc(bal & ((1u << lane) - 1u));
            S.items[base + off] = jreg[k];
        }
    }
    WBAR();
#pragma unroll
    for (int k = 0; k < NEWS/2; ++k) {
        int j0 = S.items[wtid + ((2*k)     << 8)];
        int j1 = S.items[wtid + ((2*k + 1) << 8)];
        jreg[2*k] = j0; jreg[2*k+1] = j1;
        mxp[k] = packf2(S.px[j0], S.px[j1]);
        myp[k] = packf2(S.py[j0], S.py[j1]);
        mzp[k] = packf2(S.pz[j0], S.pz[j1]);
        ml[2*k]   = S.slbl[j0];
        ml[2*k+1] = S.slbl[j1];
    }
}

__global__ void __launch_bounds__(NT, 1)
frustum_cluster_kernel(const float* __restrict__ pts,
                       const int*   __restrict__ lbl,
                       const float* __restrict__ anchors,
                       float* __restrict__ out)
{
    extern __shared__ char raw[];
    Smem& S = *reinterpret_cast<Smem*>(raw);

    const int tid  = threadIdx.x;
    const int wid  = tid >> 5;
    const int lane = tid & 31;
    const float THR = __int_as_float(ANGLE_THR_BITS);

    // ---------------- init ----------------
    for (int j = tid; j < N; j += NT) {
        S.px[j]   = pts[3*j + 0];
        S.py[j]   = pts[3*j + 1];
        S.pz[j]   = pts[3*j + 2];
        S.slbl[j] = lbl[j];
        S.selq[j] = -1;
    }
    if (tid < 10) {
        float l = anchors[tid*3+0], w = anchors[tid*3+1], h = anchors[tid*3+2];
        S.amdxy[tid] = fmaxf(l, w);
        S.amdz[tid]  = h;
        S.ar2[tid]   = __fdiv_rn(norm3_xla(l, w, h), 2.0f);
    }
    if (tid == 0) {
        S.sdl[0]   = 0;
        S.ccls[0]  = lbl[0];
        S.order[0] = 0;                      // member list = {0}
        // binary search: largest x with acos_xla(x) >= THR
        unsigned lo = ford(-1.0f), hi = ford(1.0f);
        while (hi - lo > 1u) {
            unsigned mid = lo + ((hi - lo) >> 1);
            if (acos_xla(ford_inv(mid)) >= THR) lo = mid; else hi = mid;
        }
        S.bval  = ford_inv(lo);
        S.ordb  = lo;
        S.flag0 = (acos_xla(0.0f) < THR) ? 1 : 0;
    }
    __syncthreads();

    if (wid == 0) {
        // ================= serial engine (warp 0): trails the workers =========
        const float    bval  = S.bval;
        const unsigned ordb  = S.ordb;
        const int      flag0 = S.flag0;
        volatile int*  vq    = S.selq;

        int   cls = S.slbl[0];
        float cx = S.px[0], cy = S.py[0], cz = S.pz[0];
        float pn = norm3_xla(cx, cy, cz);
        int    lab = 0, cnt = 1, mcnt = 1;
        double sx = (double)cx, sy = (double)cy, sz = (double)cz;

        for (int step = 0; step < N - 1; ++step) {
            // ---- angle pass over current member list (independent of sel) ----
            unsigned xmb = 0xFFFFFFFFu;
            for (int i = lane; i < mcnt; i += 32) {
                int j = S.order[i];
                float dx = __fsub_rn(S.px[j], cx);
                float dy = __fsub_rn(S.py[j], cy);
                float dz = __fsub_rn(S.pz[j], cz);
                float d  = norm3_xla(dx, dy, dz);
                float dt = -(__fadd_rn(__fadd_rn(__fmul_rn(cx,dx), __fmul_rn(cy,dy)),
                                       __fmul_rn(cz,dz)));
                float den = __fadd_rn(__fmul_rn(pn, d), 1e-8f);
                xmb = min(xmb, ford(__fdiv_rn(dt, den)));
            }
            xmb = __reduce_min_sync(FULLMASK, xmb);
            float xc = fminf(fmaxf(ford_inv(xmb), -1.0f), 1.0f);
            bool angflag;
            if (xc == 0.0f) {
                angflag = (flag0 != 0);
            } else {
                long dlt = (long)ford(xc) - (long)ordb;
                if (dlt > -65536 && dlt < 65536) angflag = (acos_xla(xc) < THR);
                else                             angflag = (xc > bval);
            }

            // ---- consume sel from the queue (workers run ahead) ----
            int sel;
            for (;;) {
                sel = vq[step];
                if (sel >= 0) break;
                __nanosleep(40);
            }

            // ---- tail decision + cluster state ----
            float cix = S.px[sel], ciy = S.py[sel], ciz = S.pz[sel];
            int   lci = S.slbl[sel];
            float ddx = __fsub_rn(cx, cix);
            float ddy = __fsub_rn(cy, ciy);
            float ddz = __fsub_rn(cz, ciz);
            float dn = norm3_xla(ddx, ddy, ddz);
            float cf = (float)cnt;
            float gx = __fdiv_rn((float)sx, cf);
            float gy = __fdiv_rn((float)sy, cf);
            float gz = __fdiv_rn((float)sz, cf);
            float en = norm3_xla(__fsub_rn(gx, cix), __fsub_rn(gy, ciy),
                                 __fsub_rn(gz, ciz));
            float a0 = S.amdxy[cls], a2 = S.amdz[cls], r2 = S.ar2[cls];
            bool newc = (fabsf(ddx) > a0) | (fabsf(ddy) > a0) | (fabsf(ddz) > a2) |
                        angflag | (lci != cls) | (dn > r2) | (en > r2);
            if (newc) {
                if (lane == 0) {
                    S.ccx[lab] = gx; S.ccy[lab] = gy; S.ccz[lab] = gz;
                    S.ccount[lab] = cnt;
                    S.ccls[lab + 1] = lci;
                }
                lab += 1;
                sx = (double)cix; sy = (double)ciy; sz = (double)ciz; cnt = 1;
                mcnt = 0;
            } else {
                sx += (double)cix; sy += (double)ciy; sz += (double)ciz; cnt += 1;
            }
            if (lane == 0) {
                S.order[mcnt] = sel;
                S.sdl[sel] = lab;
            }
            mcnt += 1;
            cls = lci;
            cx = cix; cy = ciy; cz = ciz;
            pn = norm3_xla(cx, cy, cz);
            __syncwarp();                    // order[] write -> next angle pass
        }
        // flush final cluster
        if (lane == 0) {
            float cf = (float)cnt;
            S.ccx[lab] = __fdiv_rn((float)sx, cf);
            S.ccy[lab] = __fdiv_rn((float)sy, cf);
            S.ccz[lab] = __fdiv_rn((float)sz, cf);
            S.ccount[lab] = cnt;
            S.bnc = lab;   // num_clusters (exclusive)
        }
    } else if (wid <= NWW) {
        // ================= candidate engine (warps 1..8, 256 threads) =========
        const int wtid = tid - 32;           // 0..255
        unsigned long long mxp[6], myp[6], mzp[6];
        int ml[12], jreg[12];
#pragma unroll
        for (int k = 0; k < 6; ++k) {
            int j0 = wtid + ((2*k)     << 8);
            int j1 = wtid + ((2*k + 1) << 8);
            mxp[k] = packf2(S.px[j0], S.px[j1]);
            myp[k] = packf2(S.py[j0], S.py[j1]);
            mzp[k] = packf2(S.pz[j0], S.pz[j1]);
            ml[2*k]   = (j0 == 0) ? -1 : S.slbl[j0];
            ml[2*k+1] = S.slbl[j1];
            jreg[2*k]   = j0;
            jreg[2*k+1] = j1;
        }

        int cls = S.slbl[0];
        float cx = S.px[0], cy = S.py[0], cz = S.pz[0];

        // stage schedule: live(step) = 3071 - step; compaction when live hits
        // exactly NEWS*WT.  1023->2048(8 slots), 2047->1024(4), 2559->512(2).
        worker_stage<6>(S, mxp, myp, mzp, ml, jreg, cls, cx, cy, cz,
                        wtid, lane, 0, 1023);
        compact_reload<12, 8>(S, mxp, myp, mzp, ml, jreg, wtid, lane);
        worker_stage<4>(S, mxp, myp, mzp, ml, jreg, cls, cx, cy, cz,
                        wtid, lane, 1023, 2047);
        compact_reload<8, 4>(S, mxp, myp, mzp, ml, jreg, wtid, lane);
        worker_stage<2>(S, mxp, myp, mzp, ml, jreg, cls, cx, cy, cz,
                        wtid, lane, 2047, 2559);
        compact_reload<4, 2>(S, mxp, myp, mzp, ml, jreg, wtid, lane);
        worker_stage<1>(S, mxp, myp, mzp, ml, jreg, cls, cx, cy, cz,
                        wtid, lane, 2559, 3071);
    }
    // warps 9..15 fall through directly to the join barrier

    __syncthreads();    // join serial + candidate engines (+ idle warps)

    const int nc = S.bnc;

    // ---------------- stable descending sort by count (bitonic, 4096 keys) -----
    unsigned* skey = reinterpret_cast<unsigned*>(S.px);
    for (int i = tid; i < 4096; i += NT) {
        unsigned key = 0;
        if (i < nc) key = ((unsigned)S.ccount[i] << 12) | (4095u - (unsigned)i);
        skey[i] = key;
    }
    for (int i = tid; i < N; i += NT) { S.remap[i] = i; S.keep[i] = 1; }
    __syncthreads();

    for (int k = 2; k <= 4096; k <<= 1) {
        for (int j = k >> 1; j > 0; j >>= 1) {
#pragma unroll
            for (int e = 0; e < 8; ++e) {
                int i = tid + e * NT;
                int ixj = i ^ j;
                if (ixj > i) {
                    unsigned a2 = skey[i], b2 = skey[ixj];
                    bool descBlock = ((i & k) == 0);
                    if (descBlock ? (a2 < b2) : (a2 > b2)) { skey[i] = b2; skey[ixj] = a2; }
                }
            }
            __syncthreads();
        }
    }
    for (int i = tid; i < N; i += NT)
        if (i < nc) S.order[i] = 4095 - (int)(skey[i] & 4095u);
    __syncthreads();

    // ---------------- group order-positions by cluster class ----------
    if (wid < 10) {
        int c = wid, total = 0;
        int limit = (nc + 31) & ~31;
        for (int s = lane; s < limit; s += 32) {
            bool mm = (s < nc) && (S.ccls[S.order[s]] == c);
            unsigned bal = __ballot_sync(FULLMASK, mm);
            total += __popc(bal);
        }
        if (lane == 0) S.clsCount[c] = total;
    }
    __syncthreads();
    if (tid == 0) {
        int acc = 0;
        for (int c = 0; c < 10; ++c) { S.clsBase[c] = acc; acc += S.clsCount[c]; }
        S.clsBase[10] = acc;
    }
    __syncthreads();
    if (wid < 10) {
        int c = wid;
        int pos = S.clsBase[c];
        int limit = (nc + 31) & ~31;
        for (int s = lane; s < limit; s += 32) {
            bool mm = (s < nc) && (S.ccls[S.order[s]] == c);
            unsigned bal = __ballot_sync(FULLMASK, mm);
            if (mm) {
                int off = __popc(bal & ((1u << lane) - 1u));
                S.items[pos + off] = s;
            }
            pos += __popc(bal);
        }
    }
    __syncthreads();

    // ---------------- merge: independent per-class sequential chains ----------
    if (wid < 10) {
        int c    = wid;
        int base = S.clsBase[c];
        int len  = S.clsBase[c + 1] - base;
        float r2c = S.ar2[c];
        for (int t = 0; t < len; ++t) {
            __syncwarp();
            int ipos = S.items[base + t];
            if (!S.keep[ipos]) continue;
            int idx = S.order[ipos];
            float ax = S.ccx[idx], ay = S.ccy[idx], az = S.ccz[idx];
            for (int s = t + 1 + lane; s < len; s += 32) {
                int jpos = S.items[base + s];
                if (S.keep[jpos]) {
                    int jidx = S.order[jpos];
                    float dd = norm3_xla(__fsub_rn(S.ccx[jidx], ax),
                                         __fsub_rn(S.ccy[jidx], ay),
                                         __fsub_rn(S.ccz[jidx], az));
                    if (dd < r2c) {
                        S.keep[jpos]  = 0;
                        S.remap[jidx] = idx;
                    }
                }
            }
        }
    }
    __syncthreads();

    // ---------------- output (float32) ----------------
    for (int i = tid; i < N; i += NT)
        out[i] = (float)S.remap[S.sdl[i]];
}

extern "C" void kernel_launch(void* const* d_in, const int* in_sizes, int n_in,
                              void* d_out, int out_size)
{
    const float* pts     = nullptr;
    const int*   lbls    = nullptr;
    const float* anchors = nullptr;
    for (int i = 0; i < n_in; ++i) {
        if      (in_sizes[i] == N * 3) pts     = (const float*)d_in[i];
        else if (in_sizes[i] == N)     lbls    = (const int*)  d_in[i];
        else if (in_sizes[i] == 30)    anchors = (const float*)d_in[i];
    }
    if (!pts)     pts     = (const float*)d_in[0];
    if (!lbls)    lbls    = (const int*)  d_in[1];
    if (!anchors) anchors = (const float*)d_in[2];

    float* out = (float*)d_out;
    (void)out_size;

    static bool attr_done = false;
    if (!attr_done) {
        cudaFuncSetAttribute(frustum_cluster_kernel,
                             cudaFuncAttributeMaxDynamicSharedMemorySize,
                             (int)sizeof(Smem));
        attr_done = true;
    }
    frustum_cluster_kernel<<<1, NT, sizeof(Smem)>>>(pts, lbls, anchors, out);
}

// round 16
// speedup vs baseline: 1.0412x; 1.0412x over previous
#include <cuda_runtime.h>
#include <math.h>
#include <cstdint>

#define N    3072
#define NT   512
#define NWW  8       // worker warps (warps 1..8)
#define WT   256     // worker threads
#define PER  12      // N / WT exactly
#define NPAIR 6      // PER/2

#define ANGLE_THR_BITS 0x3FC90FDB   // f32(pi/2)
#define FULLMASK 0xffffffffu
#define INF_F  (__int_as_float(0x7f800000))
#define INFB   0x7f800000u

struct Smem {
    float px[N], py[N], pz[N];     // points (px reused as sort keys later)
    int   slbl[N];                 // per-point class
    int   sdl[N];                  // per-point cluster label
    float ccx[N], ccy[N], ccz[N];  // per-cluster centres
    int   ccount[N], ccls[N];      // per-cluster size / class
    int   order[N];                // scan: member list; post: sort order
    int   items[N];                // post: class lists
    int   remap[N];                // post: merge remap
    int   selq[N];                 // sel sequence queue (workers -> warp 0)
    unsigned char keep[N];
    unsigned p1A[16], pIdxA[16], p2A[16], pAll[16], pMax[16], p1B[16], psel[16];
    float amdxy[10], amdz[10], ar2[10];
    int   clsCount[10], clsBase[11];
    int   bnc;
    float bval; unsigned ordb; int flag0;   // angle threshold data
};

__device__ __forceinline__ float norm3_xla(float x, float y, float z) {
    float s = __fadd_rn(__fadd_rn(__fmul_rn(x, x), __fmul_rn(y, y)), __fmul_rn(z, z));
    return __fsqrt_rn(s);
}
// XLA acos lowering: 2*atan2(sqrt(1-x*x), 1+x); pi at x==-1. Same libdevice atan2f
// as the reference -> bit-identical.
__device__ __forceinline__ float acos_xla(float x) {
    float s = __fsqrt_rn(__fsub_rn(1.0f, __fmul_rn(x, x)));
    float r = 2.0f * atan2f(s, __fadd_rn(1.0f, x));
    if (x == -1.0f) r = __int_as_float(0x40490FDB);
    return r;
}
__device__ __forceinline__ unsigned ford(float f) {
    unsigned u = __float_as_uint(f);
    return (u & 0x80000000u) ? ~u : (u | 0x80000000u);
}
__device__ __forceinline__ float ford_inv(unsigned o) {
    unsigned u = (o & 0x80000000u) ? (o ^ 0x80000000u) : ~o;
    return __uint_as_float(u);
}

// packed f32x2 helpers (two independent IEEE-RN f32 ops per instruction)
__device__ __forceinline__ unsigned long long packf2(float lo, float hi) {
    unsigned long long r;
    asm("mov.b64 %0, {%1, %2};" : "=l"(r) : "f"(lo), "f"(hi));
    return r;
}
__device__ __forceinline__ void unpackf2(unsigned long long p, float& lo, float& hi) {
    asm("mov.b64 {%0, %1}, %2;" : "=f"(lo), "=f"(hi) : "l"(p));
}
__device__ __forceinline__ unsigned long long addf2(unsigned long long a, unsigned long long b) {
    unsigned long long r;
    asm("add.rn.f32x2 %0, %1, %2;" : "=l"(r) : "l"(a), "l"(b));
    return r;
}
__device__ __forceinline__ unsigned long long mulf2(unsigned long long a, unsigned long long b) {
    unsigned long long r;
    asm("mul.rn.f32x2 %0, %1, %2;" : "=l"(r) : "l"(a), "l"(b));
    return r;
}

__global__ void __launch_bounds__(NT, 1)
frustum_cluster_kernel(const float* __restrict__ pts,
                       const int*   __restrict__ lbl,
                       const float* __restrict__ anchors,
                       float* __restrict__ out)
{
    extern __shared__ char raw[];
    Smem& S = *reinterpret_cast<Smem*>(raw);

    const int tid  = threadIdx.x;
    const int wid  = tid >> 5;
    const int lane = tid & 31;
    const float THR = __int_as_float(ANGLE_THR_BITS);

    // ---------------- init ----------------
    for (int j = tid; j < N; j += NT) {
        S.px[j]   = pts[3*j + 0];
        S.py[j]   = pts[3*j + 1];
        S.pz[j]   = pts[3*j + 2];
        S.slbl[j] = lbl[j];
        S.selq[j] = -1;
    }
    if (tid < 10) {
        float l = anchors[tid*3+0], w = anchors[tid*3+1], h = anchors[tid*3+2];
        S.amdxy[tid] = fmaxf(l, w);
        S.amdz[tid]  = h;
        S.ar2[tid]   = __fdiv_rn(norm3_xla(l, w, h), 2.0f);
    }
    if (tid == 0) {
        S.sdl[0]   = 0;
        S.ccls[0]  = lbl[0];
        S.order[0] = 0;                      // member list = {0}
        // binary search: largest x with acos_xla(x) >= THR
        unsigned lo = ford(-1.0f), hi = ford(1.0f);
        while (hi - lo > 1u) {
            unsigned mid = lo + ((hi - lo) >> 1);
            if (acos_xla(ford_inv(mid)) >= THR) lo = mid; else hi = mid;
        }
        S.bval  = ford_inv(lo);
        S.ordb  = lo;
        S.flag0 = (acos_xla(0.0f) < THR) ? 1 : 0;
    }
    __syncthreads();

    if (wid == 0) {
        // ================= serial engine (warp 0): trails the workers =========
        const float    bval  = S.bval;
        const unsigned ordb  = S.ordb;
        const int      flag0 = S.flag0;
        volatile int*  vq    = S.selq;

        int   cls = S.slbl[0];
        float cx = S.px[0], cy = S.py[0], cz = S.pz[0];
        float pn = norm3_xla(cx, cy, cz);
        int    lab = 0, cnt = 1, mcnt = 1;
        double sx = (double)cx, sy = (double)cy, sz = (double)cz;

        for (int step = 0; step < N - 1; ++step) {
            // ---- angle pass over current member list (independent of sel) ----
            unsigned xmb = 0xFFFFFFFFu;
            for (int i = lane; i < mcnt; i += 32) {
                int j = S.order[i];
                float dx = __fsub_rn(S.px[j], cx);
                float dy = __fsub_rn(S.py[j], cy);
                float dz = __fsub_rn(S.pz[j], cz);
                float d  = norm3_xla(dx, dy, dz);
                float dt = -(__fadd_rn(__fadd_rn(__fmul_rn(cx,dx), __fmul_rn(cy,dy)),
                                       __fmul_rn(cz,dz)));
                float den = __fadd_rn(__fmul_rn(pn, d), 1e-8f);
                xmb = min(xmb, ford(__fdiv_rn(dt, den)));
            }
            xmb = __reduce_min_sync(FULLMASK, xmb);
            float xc = fminf(fmaxf(ford_inv(xmb), -1.0f), 1.0f);
            bool angflag;
            if (xc == 0.0f) {
                angflag = (flag0 != 0);
            } else {
                long dlt = (long)ford(xc) - (long)ordb;
                if (dlt > -65536 && dlt < 65536) angflag = (acos_xla(xc) < THR);
                else                             angflag = (xc > bval);
            }

            // ---- consume sel from the queue (workers run ahead) ----
            int sel;
            for (;;) {
                sel = vq[step];
                if (sel >= 0) break;
                __nanosleep(40);
            }

            // ---- tail decision + cluster state ----
            float cix = S.px[sel], ciy = S.py[sel], ciz = S.pz[sel];
            int   lci = S.slbl[sel];
            float ddx = __fsub_rn(cx, cix);
            float ddy = __fsub_rn(cy, ciy);
            float ddz = __fsub_rn(cz, ciz);
            float dn = norm3_xla(ddx, ddy, ddz);
            float cf = (float)cnt;
            float gx = __fdiv_rn((float)sx, cf);
            float gy = __fdiv_rn((float)sy, cf);
            float gz = __fdiv_rn((float)sz, cf);
            float en = norm3_xla(__fsub_rn(gx, cix), __fsub_rn(gy, ciy),
                                 __fsub_rn(gz, ciz));
            float a0 = S.amdxy[cls], a2 = S.amdz[cls], r2 = S.ar2[cls];
            bool newc = (fabsf(ddx) > a0) | (fabsf(ddy) > a0) | (fabsf(ddz) > a2) |
                        angflag | (lci != cls) | (dn > r2) | (en > r2);
            if (newc) {
                if (lane == 0) {
                    S.ccx[lab] = gx; S.ccy[lab] = gy; S.ccz[lab] = gz;
                    S.ccount[lab] = cnt;
                    S.ccls[lab + 1] = lci;
                }
                lab += 1;
                sx = (double)cix; sy = (double)ciy; sz = (double)ciz; cnt = 1;
                mcnt = 0;
            } else {
                sx += (double)cix; sy += (double)ciy; sz += (double)ciz; cnt += 1;
            }
            if (lane == 0) {
                S.order[mcnt] = sel;
                S.sdl[sel] = lab;
            }
            mcnt += 1;
            cls = lci;
            cx = cix; cy = ciy; cz = ciz;
            pn = norm3_xla(cx, cy, cz);
            __syncwarp();                    // order[] write -> next angle pass
        }
        // flush final cluster
        if (lane == 0) {
            float cf = (float)cnt;
            S.ccx[lab] = __fdiv_rn((float)sx, cf);
            S.ccy[lab] = __fdiv_rn((float)sy, cf);
            S.ccz[lab] = __fdiv_rn((float)sz, cf);
            S.ccount[lab] = cnt;
            S.bnc = lab;   // num_clusters (exclusive)
        }
    } else if (wid <= NWW) {
        // ================= candidate engine (warps 1..8, 256 threads) =========
        const int wtid = tid - 32;           // 0..255
        unsigned long long mxp[NPAIR], myp[NPAIR], mzp[NPAIR];
        int ml[PER];
#pragma unroll
        for (int k = 0; k < NPAIR; ++k) {
            int j0 = wtid + ((2*k)     << 8);
            int j1 = wtid + ((2*k + 1) << 8);
            mxp[k] = packf2(S.px[j0], S.px[j1]);
            myp[k] = packf2(S.py[j0], S.py[j1]);
            mzp[k] = packf2(S.pz[j0], S.pz[j1]);
            ml[2*k]   = (j0 == 0) ? -1 : S.slbl[j0];
            ml[2*k+1] = S.slbl[j1];
        }

        int cls = S.slbl[0];
        float cx = S.px[0], cy = S.py[0], cz = S.pz[0];

        for (int step = 0; step < N - 1; ++step) {
            unsigned long long ncxp = packf2(-cx, -cx);
            unsigned long long ncyp = packf2(-cy, -cy);
            unsigned long long nczp = packf2(-cz, -cz);

            // ---- pass 1: packed dists; minA(+idx,+min2), minAll, max ----
            float m1A = INF_F, m2A = INF_F, mAll = INF_F;
            unsigned maxb = 0u;               // unsigned-0 sentinel (s >= 0)
            unsigned idxA = 0xFFFFFFFFu;
#pragma unroll
            for (int k = 0; k < NPAIR; ++k) {
                unsigned long long dxp = addf2(mxp[k], ncxp);
                unsigned long long dyp = addf2(myp[k], ncyp);
                unsigned long long dzp = addf2(mzp[k], nczp);
                unsigned long long sp  = addf2(addf2(mulf2(dxp,dxp), mulf2(dyp,dyp)),
                                               mulf2(dzp,dzp));
                float s0, s1;
                unpackf2(sp, s0, s1);
#pragma unroll
                for (int h = 0; h < 2; ++h) {
                    float s = (h == 0) ? s0 : s1;
                    int   l = ml[2*k + h];
                    unsigned idx = (unsigned)(wtid + ((2*k + h) << 8));
                    bool isA  = (l == cls);
                    bool live = (l >= 0);
                    float sA  = isA  ? s : INF_F;
                    float sL  = live ? s : INF_F;
                    maxb = max(maxb, live ? __float_as_uint(s) : 0u);
                    bool lt = (sA < m1A);
                    idxA = lt ? idx : idxA;
                    m2A  = fminf(m2A, fmaxf(m1A, sA));
                    m1A  = fminf(m1A, sA);
                    mAll = fminf(mAll, sL);
                }
            }
            // warp-level combine
            unsigned b1A = __reduce_min_sync(FULLMASK, __float_as_uint(m1A));
            unsigned bi  = (__float_as_uint(m1A) == b1A) ? idxA : 0xFFFFFFFFu;
            unsigned bIdxA = __reduce_min_sync(FULLMASK, bi);
            {   // warp second-min with duplicate handling
                unsigned eq  = __ballot_sync(FULLMASK, __float_as_uint(m1A) == b1A);
                unsigned c2  = (__float_as_uint(m1A) == b1A) ? __float_as_uint(m2A)
                                                             : __float_as_uint(m1A);
                unsigned b2A = __reduce_min_sync(FULLMASK, c2);
                if (__popc(eq) >= 2) b2A = b1A;
                unsigned bAll = __reduce_min_sync(FULLMASK, __float_as_uint(mAll));
                unsigned bMx  = __reduce_max_sync(FULLMASK, maxb);
                if (lane == 0) {
                    S.p1A[wid] = b1A; S.pIdxA[wid] = bIdxA; S.p2A[wid] = b2A;
                    S.pAll[wid] = bAll; S.pMax[wid] = bMx;
                }
            }
            asm volatile("bar.sync 1, %0;" :: "r"(WT) : "memory");   // THE barrier

            // cross-warp combine (all workers, redundant -> identical results)
            unsigned g1A, gIdxA, g2A, gAll, gMx;
            {
                bool ok = (lane >= 1 && lane <= NWW);
                unsigned r1 = ok ? S.p1A[lane]  : INFB;
                unsigned ri = ok ? S.pIdxA[lane]: 0xFFFFFFFFu;
                unsigned r2 = ok ? S.p2A[lane]  : INFB;
                unsigned ra = ok ? S.pAll[lane] : INFB;
                unsigned rm = ok ? S.pMax[lane] : 0u;
                g1A = __reduce_min_sync(FULLMASK, r1);
                gIdxA = __reduce_min_sync(FULLMASK,
                            (ok && r1 == g1A) ? ri : 0xFFFFFFFFu);
                unsigned eq = __ballot_sync(FULLMASK, ok && r1 == g1A);
                unsigned c2 = ok ? ((r1 == g1A) ? r2 : r1) : INFB;
                g2A = __reduce_min_sync(FULLMASK, c2);
                if (__popc(eq) >= 2) g2A = g1A;
                gAll = __reduce_min_sync(FULLMASK, ra);
                gMx  = __reduce_max_sync(FULLMASK, rm);
            }

            const bool hasA = (g1A != INFB);
            const float dA   = __fsqrt_rn(__uint_as_float(g1A));  // inf if !hasA
            const float dmin = __fsqrt_rn(__uint_as_float(gAll)); // min over all
            const float dmax = __fsqrt_rn(__uint_as_float(gMx));
            const float Dn   = __fadd_rn(__fsub_rn(dmax, dmin), 1e-8f);
            const float x1   = __fsub_rn(dA, dmin);   // numerator of costA

            int sel = -1;
            bool fast = false;
            if (hasA && x1 <= __fmul_rd(Dn, 0.999998f)) {
                // costA = fl(x1/Dn) < 1 certified (no division needed).
                // s-space admission bound derived directly from x1:
                // any cost_j <= costA has fl(d_j-dmin) <= x1*(1+2.4e-7)+tiny.
                float xa = __fmul_ru(x1, 1.000001f);
                float xb = __fadd_ru(xa, 1e-37f);
                float dHi = __fmul_ru(__fadd_ru(dmin, xb), 1.0000005f);
                float thrSA = __fmul_ru(__fmul_ru(dHi, dHi), 1.0000005f);
                if (thrSA < __uint_as_float(g2A)) { fast = true; sel = (int)gIdxA; }
            }

            if (!fast) {
                // ---- slow path (rare, block-uniform): exact generic logic ----
                // sweep for class-B min (not tracked in pass 1)
                float m1B = INF_F;
#pragma unroll
                for (int k = 0; k < NPAIR; ++k) {
                    unsigned long long dxp = addf2(mxp[k], ncxp);
                    unsigned long long dyp = addf2(myp[k], ncyp);
                    unsigned long long dzp = addf2(mzp[k], nczp);
                    unsigned long long sp  = addf2(addf2(mulf2(dxp,dxp),
                                                         mulf2(dyp,dyp)),
                                                   mulf2(dzp,dzp));
                    float s0, s1;
                    unpackf2(sp, s0, s1);
#pragma unroll
                    for (int h = 0; h < 2; ++h) {
                        float s = (h == 0) ? s0 : s1;
                        int   l = ml[2*k + h];
                        if (l >= 0 && l != cls) m1B = fminf(m1B, s);
                    }
                }
                unsigned b1B = __reduce_min_sync(FULLMASK, __float_as_uint(m1B));
                if (lane == 0) S.p1B[wid] = b1B;
                asm volatile("bar.sync 1, %0;" :: "r"(WT) : "memory");
                unsigned g1B;
                {
                    bool ok = (lane >= 1 && lane <= NWW);
                    unsigned rb = ok ? S.p1B[lane] : INFB;
                    g1B = __reduce_min_sync(FULLMASK, rb);
                }
                const bool hasB = (g1B != INFB);
                const float dB = __fsqrt_rn(__uint_as_float(g1B));

                float costA = INF_F, costB = INF_F;
                if (hasA) costA = __fdiv_rn(x1, Dn);
                if (hasB) costB = __fadd_rn(__fdiv_rn(__fsub_rn(dB, dmin), Dn), 1.0f);
                float cstar = fminf(costA, costB);
                float thrSA = -1.0f, thrSB = -1.0f;
                if (hasA && costA == cstar) {
                    float x = __fmul_ru(costA, Dn);
                    x = __fmul_ru(x, 1.000001f);
                    x = __fadd_ru(x, 1e-37f);
                    float dHi = __fmul_ru(__fadd_ru(dmin, x), 1.0000005f);
                    thrSA = __fmul_ru(__fmul_ru(dHi, dHi), 1.0000005f);
                }
                if (hasB && costB == cstar) {
                    float qHi = __fadd_ru(cstar, -1.0f);           // exact (Sterbenz)
                    qHi = __fadd_ru(qHi, __fadd_ru(__fmul_ru(cstar, 3e-7f), 1e-37f));
                    float x = __fmul_ru(qHi, Dn);
                    x = __fmul_ru(x, 1.000001f);
                    x = __fadd_ru(x, 1e-37f);
                    float dHi = __fmul_ru(__fadd_ru(dmin, x), 1.0000005f);
                    thrSB = __fmul_ru(__fmul_ru(dHi, dHi), 1.0000005f);
                }
                unsigned best = 0xFFFFFFFFu;
#pragma unroll
                for (int k = 0; k < NPAIR; ++k) {
                    unsigned long long dxp = addf2(mxp[k], ncxp);
                    unsigned long long dyp = addf2(myp[k], ncyp);
                    unsigned long long dzp = addf2(mzp[k], nczp);
                    unsigned long long sp  = addf2(addf2(mulf2(dxp,dxp),
                                                         mulf2(dyp,dyp)),
                                                   mulf2(dzp,dzp));
                    float s0, s1;
                    unpackf2(sp, s0, s1);
#pragma unroll
                    for (int h = 0; h < 2; ++h) {
                        float s = (h == 0) ? s0 : s1;
                        int   l = ml[2*k + h];
                        bool live = (l >= 0);
                        bool isA  = (l == cls);
                        float thr = isA ? thrSA : thrSB;
                        if (live && s <= thr) {
                            float d = __fsqrt_rn(s);
                            float q = __fdiv_rn(__fsub_rn(d, dmin), Dn);
                            float c = isA ? q : __fadd_rn(q, 1.0f);
                            if (c == cstar)
                                best = min(best, (unsigned)(wtid + ((2*k + h) << 8)));
                        }
                    }
                }
                best = __reduce_min_sync(FULLMASK, best);
                if (lane == 0) S.psel[wid] = best;
                asm volatile("bar.sync 1, %0;" :: "r"(WT) : "memory");
                {
                    bool ok = (lane >= 1 && lane <= NWW);
                    unsigned v = ok ? S.psel[lane] : 0xFFFFFFFFu;
                    sel = (int)__reduce_min_sync(FULLMASK, v);
                }
                if (sel < 0) sel = (int)gIdxA;   // defensive: never publish -1
            }

            // publish sel to the serial engine (one writer)
            if (tid == 32) ((volatile int*)S.selq)[step] = sel;

            // advance worker state: poison owned slot
            {
                int dlt = sel - wtid;
                if (dlt >= 0 && (dlt & 255) == 0) ml[dlt >> 8] = -1;
            }
            cls = S.slbl[sel];
            cx = S.px[sel]; cy = S.py[sel]; cz = S.pz[sel];
        }
    }
    // warps 9..15 fall through directly to the join barrier

    __syncthreads();    // join serial + candidate engines (+ idle warps)

    const int nc = S.bnc;

    // ---------------- stable descending sort by count (bitonic, 4096 keys) -----
    unsigned* skey = reinterpret_cast<unsigned*>(S.px);
    for (int i = tid; i < 4096; i += NT) {
        unsigned key = 0;
        if (i < nc) key = ((unsigned)S.ccount[i] << 12) | (4095u - (unsigned)i);
        skey[i] = key;
    }
    for (int i = tid; i < N; i += NT) { S.remap[i] = i; S.keep[i] = 1; }
    __syncthreads();

    for (int k = 2; k <= 4096; k <<= 1) {
        for (int j = k >> 1; j > 0; j >>= 1) {
#pragma unroll
            for (int e = 0; e < 8; ++e) {
                int i = tid + e * NT;
                int ixj = i ^ j;
                if (ixj > i) {
                    unsigned a2 = skey[i], b2 = skey[ixj];
                    bool descBlock = ((i & k) == 0);
                    if (descBlock ? (a2 < b2) : (a2 > b2)) { skey[i] = b2; skey[ixj] = a2; }
                }
            }
            __syncthreads();
        }
    }
    for (int i = tid; i < N; i += NT)
        if (i < nc) S.order[i] = 4095 - (int)(skey[i] & 4095u);
    __syncthreads();

    // ---------------- group order-positions by cluster class ----------
    if (wid < 10) {
        int c = wid, total = 0;
        int limit = (nc + 31) & ~31;
        for (int s = lane; s < limit; s += 32) {
            bool mm = (s < nc) && (S.ccls[S.order[s]] == c);
            unsigned bal = __ballot_sync(FULLMASK, mm);
            total += __popc(bal);
        }
        if (lane == 0) S.clsCount[c] = total;
    }
    __syncthreads();
    if (tid == 0) {
        int acc = 0;
        for (int c = 0; c < 10; ++c) { S.clsBase[c] = acc; acc += S.clsCount[c]; }
        S.clsBase[10] = acc;
    }
    __syncthreads();
    if (wid < 10) {
        int c = wid;
        int pos = S.clsBase[c];
        int limit = (nc + 31) & ~31;
        for (int s = lane; s < limit; s += 32) {
            bool mm = (s < nc) && (S.ccls[S.order[s]] == c);
            unsigned bal = __ballot_sync(FULLMASK, mm);
            if (mm) {
                int off = __popc(bal & ((1u << lane) - 1u));
                S.items[pos + off] = s;
            }
            pos += __popc(bal);
        }
    }
    __syncthreads();

    // ---------------- merge: independent per-class sequential chains ----------
    if (wid < 10) {
        int c    = wid;
        int base = S.clsBase[c];
        int len  = S.clsBase[c + 1] - base;
        float r2c = S.ar2[c];
        for (int t = 0; t < len; ++t) {
            __syncwarp();
            int ipos = S.items[base + t];
            if (!S.keep[ipos]) continue;
            int idx = S.order[ipos];
            float ax = S.ccx[idx], ay = S.ccy[idx], az = S.ccz[idx];
            for (int s = t + 1 + lane; s < len; s += 32) {
                int jpos = S.items[base + s];
                if (S.keep[jpos]) {
                    int jidx = S.order[jpos];
                    float dd = norm3_xla(__fsub_rn(S.ccx[jidx], ax),
                                         __fsub_rn(S.ccy[jidx], ay),
                                         __fsub_rn(S.ccz[jidx], az));
                    if (dd < r2c) {
                        S.keep[jpos]  = 0;
                        S.remap[jidx] = idx;
                    }
                }
            }
        }
    }
    __syncthreads();

    // ---------------- output (float32) ----------------
    for (int i = tid; i < N; i += NT)
        out[i] = (float)S.remap[S.sdl[i]];
}

extern "C" void kernel_launch(void* const* d_in, const int* in_sizes, int n_in,
                              void* d_out, int out_size)
{
    const float* pts     = nullptr;
    const int*   lbls    = nullptr;
    const float* anchors = nullptr;
    for (int i = 0; i < n_in; ++i) {
        if      (in_sizes[i] == N * 3) pts     = (const float*)d_in[i];
        else if (in_sizes[i] == N)     lbls    = (const int*)  d_in[i];
        else if (in_sizes[i] == 30)    anchors = (const float*)d_in[i];
    }
    if (!pts)     pts     = (const float*)d_in[0];
    if (!lbls)    lbls    = (const int*)  d_in[1];
    if (!anchors) anchors = (const float*)d_in[2];

    float* out = (float*)d_out;
    (void)out_size;

    static bool attr_done = false;
    if (!attr_done) {
        cudaFuncSetAttribute(frustum_cluster_kernel,
                             cudaFuncAttributeMaxDynamicSharedMemorySize,
                             (int)sizeof(Smem));
        attr_done = true;
    }
    frustum_cluster_kernel<<<1, NT, sizeof(Smem)>>>(pts, lbls, anchors, out);
}

// round 17
// speedup vs baseline: 1.0413x; 1.0001x over previous
#include <cuda_runtime.h>
#include <math.h>
#include <cstdint>

#define N    3072
#define NT   512
#define NWW  8       // worker warps (warps 1..8)
#define WT   256     // worker threads
#define PER  12      // N / WT exactly
#define NPAIR 6      // PER/2

#define ANGLE_THR_BITS 0x3FC90FDB   // f32(pi/2)
#define FULLMASK 0xffffffffu
#define INF_F  (__int_as_float(0x7f800000))
#define INFB   0x7f800000u

struct Smem {
    float px[N], py[N], pz[N];     // points (px reused as sort keys later)
    int   slbl[N];                 // per-point class
    int   sdl[N];                  // per-point cluster label
    float ccx[N], ccy[N], ccz[N];  // per-cluster centres
    int   ccount[N], ccls[N];      // per-cluster size / class
    int   order[N];                // scan: member list; post: sort order
    int   items[N];                // post: class lists
    int   remap[N];                // post: merge remap
    int   selq[N];                 // sel sequence queue (workers -> warp 0)
    unsigned char keep[N];
    unsigned p1A[16], pIdxA[16], p2A[16], pAll[16], pMax[16], p1B[16], psel[16];
    float amdxy[10], amdz[10], ar2[10];
    int   clsCount[10], clsBase[11];
    int   bnc;
    float bval; unsigned ordb; int flag0;   // angle threshold data
};

__device__ __forceinline__ float norm3_xla(float x, float y, float z) {
    float s = __fadd_rn(__fadd_rn(__fmul_rn(x, x), __fmul_rn(y, y)), __fmul_rn(z, z));
    return __fsqrt_rn(s);
}
// XLA acos lowering: 2*atan2(sqrt(1-x*x), 1+x); pi at x==-1. Same libdevice atan2f
// as the reference -> bit-identical.
__device__ __forceinline__ float acos_xla(float x) {
    float s = __fsqrt_rn(__fsub_rn(1.0f, __fmul_rn(x, x)));
    float r = 2.0f * atan2f(s, __fadd_rn(1.0f, x));
    if (x == -1.0f) r = __int_as_float(0x40490FDB);
    return r;
}
__device__ __forceinline__ unsigned ford(float f) {
    unsigned u = __float_as_uint(f);
    return (u & 0x80000000u) ? ~u : (u | 0x80000000u);
}
__device__ __forceinline__ float ford_inv(unsigned o) {
    unsigned u = (o & 0x80000000u) ? (o ^ 0x80000000u) : ~o;
    return __uint_as_float(u);
}

// packed f32x2 helpers (two independent IEEE-RN f32 ops per instruction)
__device__ __forceinline__ unsigned long long packf2(float lo, float hi) {
    unsigned long long r;
    asm("mov.b64 %0, {%1, %2};" : "=l"(r) : "f"(lo), "f"(hi));
    return r;
}
__device__ __forceinline__ void unpackf2(unsigned long long p, float& lo, float& hi) {
    asm("mov.b64 {%0, %1}, %2;" : "=f"(lo), "=f"(hi) : "l"(p));
}
__device__ __forceinline__ unsigned long long addf2(unsigned long long a, unsigned long long b) {
    unsigned long long r;
    asm("add.rn.f32x2 %0, %1, %2;" : "=l"(r) : "l"(a), "l"(b));
    return r;
}
__device__ __forceinline__ unsigned long long mulf2(unsigned long long a, unsigned long long b) {
    unsigned long long r;
    asm("mul.rn.f32x2 %0, %1, %2;" : "=l"(r) : "l"(a), "l"(b));
    return r;
}

__global__ void __launch_bounds__(NT, 1)
frustum_cluster_kernel(const float* __restrict__ pts,
                       const int*   __restrict__ lbl,
                       const float* __restrict__ anchors,
                       float* __restrict__ out)
{
    extern __shared__ char raw[];
    Smem& S = *reinterpret_cast<Smem*>(raw);

    const int tid  = threadIdx.x;
    const int wid  = tid >> 5;
    const int lane = tid & 31;
    const float THR = __int_as_float(ANGLE_THR_BITS);

    // ---------------- init ----------------
    for (int j = tid; j < N; j += NT) {
        S.px[j]   = pts[3*j + 0];
        S.py[j]   = pts[3*j + 1];
        S.pz[j]   = pts[3*j + 2];
        S.slbl[j] = lbl[j];
        S.selq[j] = -1;
    }
    if (tid < 10) {
        float l = anchors[tid*3+0], w = anchors[tid*3+1], h = anchors[tid*3+2];
        S.amdxy[tid] = fmaxf(l, w);
        S.amdz[tid]  = h;
        S.ar2[tid]   = __fdiv_rn(norm3_xla(l, w, h), 2.0f);
    }
    if (tid == 0) {
        S.sdl[0]   = 0;
        S.ccls[0]  = lbl[0];
        S.order[0] = 0;                      // member list = {0}
        // binary search: largest x with acos_xla(x) >= THR
        unsigned lo = ford(-1.0f), hi = ford(1.0f);
        while (hi - lo > 1u) {
            unsigned mid = lo + ((hi - lo) >> 1);
            if (acos_xla(ford_inv(mid)) >= THR) lo = mid; else hi = mid;
        }
        S.bval  = ford_inv(lo);
        S.ordb  = lo;
        S.flag0 = (acos_xla(0.0f) < THR) ? 1 : 0;
    }
    __syncthreads();

    if (wid == 0) {
        // ================= serial engine (warp 0): trails the workers =========
        const float    bval  = S.bval;
        const unsigned ordb  = S.ordb;
        const int      flag0 = S.flag0;
        volatile int*  vq    = S.selq;

        int   cls = S.slbl[0];
        float cx = S.px[0], cy = S.py[0], cz = S.pz[0];
        float pn = norm3_xla(cx, cy, cz);
        int    lab = 0, cnt = 1, mcnt = 1;
        double sx = (double)cx, sy = (double)cy, sz = (double)cz;

        for (int step = 0; step < N - 1; ++step) {
            // ---- angle pass over current member list (independent of sel) ----
            unsigned xmb = 0xFFFFFFFFu;
            for (int i = lane; i < mcnt; i += 32) {
                int j = S.order[i];
                float dx = __fsub_rn(S.px[j], cx);
                float dy = __fsub_rn(S.py[j], cy);
                float dz = __fsub_rn(S.pz[j], cz);
                float d  = norm3_xla(dx, dy, dz);
                float dt = -(__fadd_rn(__fadd_rn(__fmul_rn(cx,dx), __fmul_rn(cy,dy)),
                                       __fmul_rn(cz,dz)));
                float den = __fadd_rn(__fmul_rn(pn, d), 1e-8f);
                xmb = min(xmb, ford(__fdiv_rn(dt, den)));
            }
            xmb = __reduce_min_sync(FULLMASK, xmb);
            float xc = fminf(fmaxf(ford_inv(xmb), -1.0f), 1.0f);
            bool angflag;
            if (xc == 0.0f) {
                angflag = (flag0 != 0);
            } else {
                long dlt = (long)ford(xc) - (long)ordb;
                if (dlt > -65536 && dlt < 65536) angflag = (acos_xla(xc) < THR);
                else                             angflag = (xc > bval);
            }

            // ---- consume sel from the queue (workers run ahead) ----
            int sel;
            for (;;) {
                sel = vq[step];
                if (sel >= 0) break;
                __nanosleep(40);
            }

            // ---- tail decision + cluster state ----
            float cix = S.px[sel], ciy = S.py[sel], ciz = S.pz[sel];
            int   lci = S.slbl[sel];
            float ddx = __fsub_rn(cx, cix);
            float ddy = __fsub_rn(cy, ciy);
            float ddz = __fsub_rn(cz, ciz);
            float dn = norm3_xla(ddx, ddy, ddz);
            float cf = (float)cnt;
            float gx = __fdiv_rn((float)sx, cf);
            float gy = __fdiv_rn((float)sy, cf);
            float gz = __fdiv_rn((float)sz, cf);
            float en = norm3_xla(__fsub_rn(gx, cix), __fsub_rn(gy, ciy),
                                 __fsub_rn(gz, ciz));
            float a0 = S.amdxy[cls], a2 = S.amdz[cls], r2 = S.ar2[cls];
            bool newc = (fabsf(ddx) > a0) | (fabsf(ddy) > a0) | (fabsf(ddz) > a2) |
                        angflag | (lci != cls) | (dn > r2) | (en > r2);
            if (newc) {
                if (lane == 0) {
                    S.ccx[lab] = gx; S.ccy[lab] = gy; S.ccz[lab] = gz;
                    S.ccount[lab] = cnt;
                    S.ccls[lab + 1] = lci;
                }
                lab += 1;
                sx = (double)cix; sy = (double)ciy; sz = (double)ciz; cnt = 1;
                mcnt = 0;
            } else {
                sx += (double)cix; sy += (double)ciy; sz += (double)ciz; cnt += 1;
            }
            if (lane == 0) {
                S.order[mcnt] = sel;
                S.sdl[sel] = lab;
            }
            mcnt += 1;
            cls = lci;
            cx = cix; cy = ciy; cz = ciz;
            pn = norm3_xla(cx, cy, cz);
            __syncwarp();                    // order[] write -> next angle pass
        }
        // flush final cluster
        if (lane == 0) {
            float cf = (float)cnt;
            S.ccx[lab] = __fdiv_rn((float)sx, cf);
            S.ccy[lab] = __fdiv_rn((float)sy, cf);
            S.ccz[lab] = __fdiv_rn((float)sz, cf);
            S.ccount[lab] = cnt;
            S.bnc = lab;   // num_clusters (exclusive)
        }
    } else if (wid <= NWW) {
        // ================= candidate engine (warps 1..8, 256 threads) =========
        const int wtid = tid - 32;           // 0..255
        unsigned long long mxp[NPAIR], myp[NPAIR], mzp[NPAIR];
        int ml[PER];
#pragma unroll
        for (int k = 0; k < NPAIR; ++k) {
            int j0 = wtid + ((2*k)     << 8);
            int j1 = wtid + ((2*k + 1) << 8);
            mxp[k] = packf2(S.px[j0], S.px[j1]);
            myp[k] = packf2(S.py[j0], S.py[j1]);
            mzp[k] = packf2(S.pz[j0], S.pz[j1]);
            ml[2*k]   = (j0 == 0) ? -1 : S.slbl[j0];
            ml[2*k+1] = S.slbl[j1];
        }

        int cls = S.slbl[0];
        float cx = S.px[0], cy = S.py[0], cz = S.pz[0];

        for (int step = 0; step < N - 1; ++step) {
            unsigned long long ncxp = packf2(-cx, -cx);
            unsigned long long ncyp = packf2(-cy, -cy);
            unsigned long long nczp = packf2(-cz, -cz);

            // ---- pass 1: packed dists; minA(+idx,+min2), minAll, max ----
            float m1A = INF_F, m2A = INF_F, mAll = INF_F;
            unsigned maxb = 0u;               // unsigned-0 sentinel (s >= 0)
            unsigned idxA = 0xFFFFFFFFu;
#pragma unroll
            for (int k = 0; k < NPAIR; ++k) {
                unsigned long long dxp = addf2(mxp[k], ncxp);
                unsigned long long dyp = addf2(myp[k], ncyp);
                unsigned long long dzp = addf2(mzp[k], nczp);
                unsigned long long sp  = addf2(addf2(mulf2(dxp,dxp), mulf2(dyp,dyp)),
                                               mulf2(dzp,dzp));
                float s0, s1;
                unpackf2(sp, s0, s1);
#pragma unroll
                for (int h = 0; h < 2; ++h) {
                    float s = (h == 0) ? s0 : s1;
                    int   l = ml[2*k + h];
                    unsigned idx = (unsigned)(wtid + ((2*k + h) << 8));
                    bool isA  = (l == cls);
                    bool live = (l >= 0);
                    float sA  = isA  ? s : INF_F;
                    float sL  = live ? s : INF_F;
                    maxb = max(maxb, live ? __float_as_uint(s) : 0u);
                    bool lt = (sA < m1A);
                    idxA = lt ? idx : idxA;
                    m2A  = fminf(m2A, fmaxf(m1A, sA));
                    m1A  = fminf(m1A, sA);
                    mAll = fminf(mAll, sL);
                }
            }
            // warp-level combine
            unsigned b1A = __reduce_min_sync(FULLMASK, __float_as_uint(m1A));
            unsigned eq  = __ballot_sync(FULLMASK, __float_as_uint(m1A) == b1A);
            // unique-winner idx fetch (valid when winner unique; ties force the
            // slow path because b2A==b1A below)
            unsigned bIdxA = __shfl_sync(FULLMASK, idxA, __ffs(eq) - 1);
            unsigned c2  = (__float_as_uint(m1A) == b1A) ? __float_as_uint(m2A)
                                                         : __float_as_uint(m1A);
            unsigned b2A = __reduce_min_sync(FULLMASK, c2);
            if (__popc(eq) >= 2) b2A = b1A;
            unsigned bAll = __reduce_min_sync(FULLMASK, __float_as_uint(mAll));
            unsigned bMx  = __reduce_max_sync(FULLMASK, maxb);
            if (lane == 0) {
                S.p1A[wid] = b1A; S.pIdxA[wid] = bIdxA; S.p2A[wid] = b2A;
                S.pAll[wid] = bAll; S.pMax[wid] = bMx;
            }
            asm volatile("bar.sync 1, %0;" :: "r"(WT) : "memory");   // THE barrier

            // cross-warp combine (all workers, redundant -> identical results)
            unsigned g1A, gIdxA, g2A, gAll, gMx;
            {
                bool ok = (lane >= 1 && lane <= NWW);
                unsigned r1 = ok ? S.p1A[lane]  : INFB;
                unsigned ri = ok ? S.pIdxA[lane]: 0xFFFFFFFFu;
                unsigned r2 = ok ? S.p2A[lane]  : INFB;
                unsigned ra = ok ? S.pAll[lane] : INFB;
                unsigned rm = ok ? S.pMax[lane] : 0u;
                g1A = __reduce_min_sync(FULLMASK, r1);
                unsigned eqX = __ballot_sync(FULLMASK, ok && r1 == g1A);
                gIdxA = __shfl_sync(FULLMASK, ri, __ffs(eqX) - 1);
                unsigned c2x = ok ? ((r1 == g1A) ? r2 : r1) : INFB;
                g2A = __reduce_min_sync(FULLMASK, c2x);
                if (__popc(eqX) >= 2) g2A = g1A;
                gAll = __reduce_min_sync(FULLMASK, ra);
                gMx  = __reduce_max_sync(FULLMASK, rm);
            }

            const bool hasA = (g1A != INFB);
            const float dA   = __fsqrt_rn(__uint_as_float(g1A));  // inf if !hasA
            const float dmin = __fsqrt_rn(__uint_as_float(gAll)); // min over all
            const float dmax = __fsqrt_rn(__uint_as_float(gMx));
            const float Dn   = __fadd_rn(__fsub_rn(dmax, dmin), 1e-8f);
            const float x1   = __fsub_rn(dA, dmin);   // numerator of costA

            int sel = -1;
            bool fast = false;
            if (hasA && x1 <= __fmul_rd(Dn, 0.999998f)) {
                // costA = fl(x1/Dn) < 1 certified (no division needed).
                // s-space admission bound derived directly from x1.
                float xa = __fmul_ru(x1, 1.000001f);
                float xb = __fadd_ru(xa, 1e-37f);
                float dHi = __fmul_ru(__fadd_ru(dmin, xb), 1.0000005f);
                float thrSA = __fmul_ru(__fmul_ru(dHi, dHi), 1.0000005f);
                if (thrSA < __uint_as_float(g2A)) { fast = true; sel = (int)gIdxA; }
            }

            if (!fast) {
                // ---- slow path (rare, block-uniform): exact generic logic ----
                float m1B = INF_F;
#pragma unroll
                for (int k = 0; k < NPAIR; ++k) {
                    unsigned long long dxp = addf2(mxp[k], ncxp);
                    unsigned long long dyp = addf2(myp[k], ncyp);
                    unsigned long long dzp = addf2(mzp[k], nczp);
                    unsigned long long sp  = addf2(addf2(mulf2(dxp,dxp),
                                                         mulf2(dyp,dyp)),
                                                   mulf2(dzp,dzp));
                    float s0, s1;
                    unpackf2(sp, s0, s1);
#pragma unroll
                    for (int h = 0; h < 2; ++h) {
                        float s = (h == 0) ? s0 : s1;
                        int   l = ml[2*k + h];
                        if (l >= 0 && l != cls) m1B = fminf(m1B, s);
                    }
                }
                unsigned b1B = __reduce_min_sync(FULLMASK, __float_as_uint(m1B));
                if (lane == 0) S.p1B[wid] = b1B;
                asm volatile("bar.sync 1, %0;" :: "r"(WT) : "memory");
                unsigned g1B;
                {
                    bool ok = (lane >= 1 && lane <= NWW);
                    unsigned rb = ok ? S.p1B[lane] : INFB;
                    g1B = __reduce_min_sync(FULLMASK, rb);
                }
                const bool hasB = (g1B != INFB);
                const float dB = __fsqrt_rn(__uint_as_float(g1B));

                float costA = INF_F, costB = INF_F;
                if (hasA) costA = __fdiv_rn(x1, Dn);
                if (hasB) costB = __fadd_rn(__fdiv_rn(__fsub_rn(dB, dmin), Dn), 1.0f);
                float cstar = fminf(costA, costB);
                float thrSA = -1.0f, thrSB = -1.0f;
                if (hasA && costA == cstar) {
                    float x = __fmul_ru(costA, Dn);
                    x = __fmul_ru(x, 1.000001f);
                    x = __fadd_ru(x, 1e-37f);
                    float dHi = __fmul_ru(__fadd_ru(dmin, x), 1.0000005f);
                    thrSA = __fmul_ru(__fmul_ru(dHi, dHi), 1.0000005f);
                }
                if (hasB && costB == cstar) {
                    float qHi = __fadd_ru(cstar, -1.0f);           // exact (Sterbenz)
                    qHi = __fadd_ru(qHi, __fadd_ru(__fmul_ru(cstar, 3e-7f), 1e-37f));
                    float x = __fmul_ru(qHi, Dn);
                    x = __fmul_ru(x, 1.000001f);
                    x = __fadd_ru(x, 1e-37f);
                    float dHi = __fmul_ru(__fadd_ru(dmin, x), 1.0000005f);
                    thrSB = __fmul_ru(__fmul_ru(dHi, dHi), 1.0000005f);
                }
                unsigned best = 0xFFFFFFFFu;
#pragma unroll
                for (int k = 0; k < NPAIR; ++k) {
                    unsigned long long dxp = addf2(mxp[k], ncxp);
                    unsigned long long dyp = addf2(myp[k], ncyp);
                    unsigned long long dzp = addf2(mzp[k], nczp);
                    unsigned long long sp  = addf2(addf2(mulf2(dxp,dxp),
                                                         mulf2(dyp,dyp)),
                                                   mulf2(dzp,dzp));
                    float s0, s1;
                    unpackf2(sp, s0, s1);
#pragma unroll
                    for (int h = 0; h < 2; ++h) {
                        float s = (h == 0) ? s0 : s1;
                        int   l = ml[2*k + h];
                        bool live = (l >= 0);
                        bool isA  = (l == cls);
                        float thr = isA ? thrSA : thrSB;
                        if (live && s <= thr) {
                            float d = __fsqrt_rn(s);
                            float q = __fdiv_rn(__fsub_rn(d, dmin), Dn);
                            float c = isA ? q : __fadd_rn(q, 1.0f);
                            if (c == cstar)
                                best = min(best, (unsigned)(wtid + ((2*k + h) << 8)));
                        }
                    }
                }
                best = __reduce_min_sync(FULLMASK, best);
                if (lane == 0) S.psel[wid] = best;
                asm volatile("bar.sync 1, %0;" :: "r"(WT) : "memory");
                {
                    bool ok = (lane >= 1 && lane <= NWW);
                    unsigned v = ok ? S.psel[lane] : 0xFFFFFFFFu;
                    sel = (int)__reduce_min_sync(FULLMASK, v);
                }
                if (sel < 0) sel = (int)gIdxA;   // defensive: never publish -1
            }

            // publish sel to the serial engine (one writer)
            if (tid == 32) ((volatile int*)S.selq)[step] = sel;

            // advance worker state: poison owned slot (CONSTANT indices only —
            // keeps ml[] in registers, avoids local-memory demotion)
#pragma unroll
            for (int k = 0; k < PER; ++k)
                if (wtid + (k << 8) == sel) ml[k] = -1;
            cls = S.slbl[sel];
            cx = S.px[sel]; cy = S.py[sel]; cz = S.pz[sel];
        }
    }
    // warps 9..15 fall through directly to the join barrier

    __syncthreads();    // join serial + candidate engines (+ idle warps)

    const int nc = S.bnc;

    // ---------------- stable descending sort by count (bitonic, 4096 keys) -----
    unsigned* skey = reinterpret_cast<unsigned*>(S.px);
    for (int i = tid; i < 4096; i += NT) {
        unsigned key = 0;
        if (i < nc) key = ((unsigned)S.ccount[i] << 12) | (4095u - (unsigned)i);
        skey[i] = key;
    }
    for (int i = tid; i < N; i += NT) { S.remap[i] = i; S.keep[i] = 1; }
    __syncthreads();

    for (int k = 2; k <= 4096; k <<= 1) {
        for (int j = k >> 1; j > 0; j >>= 1) {
#pragma unroll
            for (int e = 0; e < 8; ++e) {
                int i = tid + e * NT;
                int ixj = i ^ j;
                if (ixj > i) {
                    unsigned a2 = skey[i], b2 = skey[ixj];
                    bool descBlock = ((i & k) == 0);
                    if (descBlock ? (a2 < b2) : (a2 > b2)) { skey[i] = b2; skey[ixj] = a2; }
                }
            }
            __syncthreads();
        }
    }
    for (int i = tid; i < N; i += NT)
        if (i < nc) S.order[i] = 4095 - (int)(skey[i] & 4095u);
    __syncthreads();

    // ---------------- group order-positions by cluster class ----------
    if (wid < 10) {
        int c = wid, total = 0;
        int limit = (nc + 31) & ~31;
        for (int s = lane; s < limit; s += 32) {
            bool mm = (s < nc) && (S.ccls[S.order[s]] == c);
            unsigned bal = __ballot_sync(FULLMASK, mm);
            total += __popc(bal);
        }
        if (lane == 0) S.clsCount[c] = total;
    }
    __syncthreads();
    if (tid == 0) {
        int acc = 0;
        for (int c = 0; c < 10; ++c) { S.clsBase[c] = acc; acc += S.clsCount[c]; }
        S.clsBase[10] = acc;
    }
    __syncthreads();
    if (wid < 10) {
        int c = wid;
        int pos = S.clsBase[c];
        int limit = (nc + 31) & ~31;
        for (int s = lane; s < limit; s += 32) {
            bool mm = (s < nc) && (S.ccls[S.order[s]] == c);
            unsigned bal = __ballot_sync(FULLMASK, mm);
            if (mm) {
                int off = __popc(bal & ((1u << lane) - 1u));
                S.items[pos + off] = s;
            }
            pos += __popc(bal);
        }
    }
    __syncthreads();

    // ---------------- merge: independent per-class sequential chains ----------
    if (wid < 10) {
        int c    = wid;
        int base = S.clsBase[c];
        int len  = S.clsBase[c + 1] - base;
        float r2c = S.ar2[c];
        for (int t = 0; t < len; ++t) {
            __syncwarp();
            int ipos = S.items[base + t];
            if (!S.keep[ipos]) continue;
            int idx = S.order[ipos];
            float ax = S.ccx[idx], ay = S.ccy[idx], az = S.ccz[idx];
            for (int s = t + 1 + lane; s < len; s += 32) {
                int jpos = S.items[base + s];
                if (S.keep[jpos]) {
                    int jidx = S.order[jpos];
                    float dd = norm3_xla(__fsub_rn(S.ccx[jidx], ax),
                                         __fsub_rn(S.ccy[jidx], ay),
                                         __fsub_rn(S.ccz[jidx], az));
                    if (dd < r2c) {
                        S.keep[jpos]  = 0;
                        S.remap[jidx] = idx;
                    }
                }
            }
        }
    }
    __syncthreads();

    // ---------------- output (float32) ----------------
    for (int i = tid; i < N; i += NT)
        out[i] = (float)S.remap[S.sdl[i]];
}

extern "C" void kernel_launch(void* const* d_in, const int* in_sizes, int n_in,
                              void* d_out, int out_size)
{
    const float* pts     = nullptr;
    const int*   lbls    = nullptr;
    const float* anchors = nullptr;
    for (int i = 0; i < n_in; ++i) {
        if      (in_sizes[i] == N * 3) pts     = (const float*)d_in[i];
        else if (in_sizes[i] == N)     lbls    = (const int*)  d_in[i];
        else if (in_sizes[i] == 30)    anchors = (const float*)d_in[i];
    }
    if (!pts)     pts     = (const float*)d_in[0];
    if (!lbls)    lbls    = (const int*)  d_in[1];
    if (!anchors) anchors = (const float*)d_in[2];

    float* out = (float*)d_out;
    (void)out_size;

    static bool attr_done = false;
    if (!attr_done) {
        cudaFuncSetAttribute(frustum_cluster_kernel,
                             cudaFuncAttributeMaxDynamicSharedMemorySize,
                             (int)sizeof(Smem));
        attr_done = true;
    }
    frustum_cluster_kernel<<<1, NT, sizeof(Smem)>>>(pts, lbls, anchors, out);
}